// round 3
// baseline (speedup 1.0000x reference)
#include <cuda_runtime.h>
#include <math.h>

// ---------------- problem constants ----------------
#define BB   2
#define NTOK 577
#define DIMM 512
#define HH   8
#define DHH  64
#define NCC  145     // ceil(577/4) compressed blocks
#define NSB  10      // ceil(577/64) select blocks
#define KSEL 4
#define SWIN 32
#define MLPD 2048
#define NCLS 1000
#define BN   (BB*NTOK)    // 1154
#define QC   8            // queries per cattn block
#define NQB  73           // ceil(577/8)
#define CM   (BB*HH*NCC)  // 2320 compress rows

#define ACT_NONE 0
#define ACT_GELU 1
#define ACT_SIG  2

// ---------------- device scratch ----------------
__device__ float g_x   [BN*DIMM];
__device__ float g_h   [BN*DIMM];
__device__ float g_q   [BN*DIMM];
__device__ float g_k   [BN*DIMM];
__device__ float g_v   [BN*DIMM];
__device__ float g_gate[BN*24];
__device__ float g_ck  [CM*DHH];
__device__ float g_cv  [CM*DHH];
__device__ float g_outc[BB*HH*NTOK*DHH];
__device__ float g_outs[BB*HH*NTOK*DHH];
__device__ int   g_selb[BB*HH*NTOK*KSEL];
__device__ float g_attn[BN*DIMM];
__device__ float g_mlp [BN*MLPD];
__device__ float g_hb  [BB*DIMM];

// ---------------- helpers ----------------
__device__ __forceinline__ float gelu_tanh(float x) {
    float x3 = x * x * x;
    return 0.5f * x * (1.0f + tanhf(0.7978845608028654f * (x + 0.044715f * x3)));
}
__device__ __forceinline__ unsigned f2tf32(float x) {
    unsigned r;
    asm("cvt.rna.tf32.f32 %0, %1;" : "=r"(r) : "f"(x));
    return r;
}
__device__ __forceinline__ void mma_tf32(float* d, const unsigned* a,
                                         const unsigned* b, const float* c) {
    asm volatile(
        "mma.sync.aligned.m16n8k8.row.col.f32.tf32.tf32.f32 "
        "{%0,%1,%2,%3}, {%4,%5,%6,%7}, {%8,%9}, {%10,%11,%12,%13};\n"
        : "=f"(d[0]), "=f"(d[1]), "=f"(d[2]), "=f"(d[3])
        : "r"(a[0]), "r"(a[1]), "r"(a[2]), "r"(a[3]),
          "r"(b[0]), "r"(b[1]),
          "f"(c[0]), "f"(c[1]), "f"(c[2]), "f"(c[3]));
}

__device__ __forceinline__ float blk_max256(float v, float* sred) {
    #pragma unroll
    for (int o = 16; o; o >>= 1) v = fmaxf(v, __shfl_xor_sync(0xffffffffu, v, o));
    __syncthreads();
    if ((threadIdx.x & 31) == 0) sred[threadIdx.x >> 5] = v;
    __syncthreads();
    float r = sred[0];
    #pragma unroll
    for (int w = 1; w < 8; w++) r = fmaxf(r, sred[w]);
    return r;
}
__device__ __forceinline__ float blk_sum256(float v, float* sred) {
    #pragma unroll
    for (int o = 16; o; o >>= 1) v += __shfl_xor_sync(0xffffffffu, v, o);
    __syncthreads();
    if ((threadIdx.x & 31) == 0) sred[threadIdx.x >> 5] = v;
    __syncthreads();
    float r = sred[0];
    #pragma unroll
    for (int w = 1; w < 8; w++) r += sred[w];
    return r;
}

// ---------------- A-side loaders for the TF32 GEMM ----------------
struct PlainA {
    const float* A; int K;
    const float* rp;
    __device__ __forceinline__ void setup(int row) { rp = A + (size_t)row * K; }
    __device__ __forceinline__ float4 fetch(int e) const {
        return *(const float4*)(rp + e);
    }
};
// compress gather: row = bh*NCC + j; col e = jj*64+d; val = (pad k)[tok] + pe
struct GatherA {
    const float* kin; const float* pe;
    const float* kbase; int j4;
    __device__ __forceinline__ void setup(int row) {
        int bh = row / NCC, j = row - bh * NCC;
        int b = bh >> 3, h = bh & 7;
        kbase = kin + (size_t)b * NTOK * DIMM + h * 64;
        j4 = j * 4;
    }
    __device__ __forceinline__ float4 fetch(int e) const {
        int jj = e >> 6, d = e & 63;
        float4 p = *(const float4*)(pe + e);
        int tok = j4 + jj;
        if (tok < NTOK) {
            float4 kv = *(const float4*)(kbase + (size_t)tok * DIMM + d);
            p.x += kv.x; p.y += kv.y; p.z += kv.z; p.w += kv.w;
        }
        return p;
    }
};

// ---------------- TF32 tensor-core GEMM body ----------------
// CTA tile 128x64, 8 warps (4x2), warp tile 32x32 (2x4 m16n8k8), TK=16, dbl-buffer.
// Requires: Nn % 64 == 0, K % 16 == 0.
template <class LD>
__device__ __forceinline__ void tgemm_body(
    LD ld, const float* __restrict__ W,
    const float* __restrict__ bias, const float* __restrict__ res,
    float* __restrict__ C, int M, int Nn, int K, int act, int row0, int col0)
{
    __shared__ unsigned As[2][16][136];
    __shared__ unsigned Bs[2][16][72];
    int tid = threadIdx.x;
    int lane = tid & 31, warp = tid >> 5;
    int wm = warp & 3, wn = warp >> 2;

    int am  = tid >> 1;            // 0..127
    int ak0 = (tid & 1) << 3;      // 0 or 8
    int arow = row0 + am;
    bool avalid = arow < M;
    if (avalid) ld.setup(arow);

    int bk = tid >> 4;             // 0..15
    int bn = (tid & 15) << 2;      // 0..60
    const float* Wp = W + (size_t)bk * Nn + col0 + bn;

    float acc[2][4][4];
    #pragma unroll
    for (int mt = 0; mt < 2; mt++)
        #pragma unroll
        for (int nt = 0; nt < 4; nt++)
            #pragma unroll
            for (int e = 0; e < 4; e++) acc[mt][nt][e] = 0.f;

    auto stageA = [&](int buf, int kt) {
        #pragma unroll
        for (int c = 0; c < 2; c++) {
            int kk = ak0 + c * 4;
            float4 v = avalid ? ld.fetch(kt * 16 + kk) : make_float4(0.f, 0.f, 0.f, 0.f);
            As[buf][kk + 0][am] = f2tf32(v.x);
            As[buf][kk + 1][am] = f2tf32(v.y);
            As[buf][kk + 2][am] = f2tf32(v.z);
            As[buf][kk + 3][am] = f2tf32(v.w);
        }
    };
    auto stageB = [&](int buf, int kt) {
        float4 v = *(const float4*)(Wp + (size_t)(kt * 16) * Nn);
        unsigned* dst = &Bs[buf][bk][bn];
        dst[0] = f2tf32(v.x); dst[1] = f2tf32(v.y);
        dst[2] = f2tf32(v.z); dst[3] = f2tf32(v.w);
    };

    stageA(0, 0); stageB(0, 0);
    __syncthreads();
    int ktiles = K >> 4;
    int r = lane >> 2, cl = lane & 3;
    for (int kt = 0; kt < ktiles; kt++) {
        int cur = kt & 1;
        if (kt + 1 < ktiles) { stageA(cur ^ 1, kt + 1); stageB(cur ^ 1, kt + 1); }
        #pragma unroll
        for (int k8 = 0; k8 < 2; k8++) {
            int kb = k8 << 3;
            unsigned af[2][4], bf[4][2];
            #pragma unroll
            for (int mt = 0; mt < 2; mt++) {
                int mb = wm * 32 + mt * 16 + r;
                af[mt][0] = As[cur][kb + cl][mb];
                af[mt][1] = As[cur][kb + cl][mb + 8];
                af[mt][2] = As[cur][kb + cl + 4][mb];
                af[mt][3] = As[cur][kb + cl + 4][mb + 8];
            }
            #pragma unroll
            for (int nt = 0; nt < 4; nt++) {
                int nb = wn * 32 + nt * 8 + r;
                bf[nt][0] = Bs[cur][kb + cl][nb];
                bf[nt][1] = Bs[cur][kb + cl + 4][nb];
            }
            #pragma unroll
            for (int mt = 0; mt < 2; mt++)
                #pragma unroll
                for (int nt = 0; nt < 4; nt++)
                    mma_tf32(acc[mt][nt], af[mt], bf[nt], acc[mt][nt]);
        }
        __syncthreads();
    }

    int cl2 = (lane & 3) * 2;
    #pragma unroll
    for (int mt = 0; mt < 2; mt++) {
        #pragma unroll
        for (int half = 0; half < 2; half++) {
            int rrow = row0 + wm * 32 + mt * 16 + r + half * 8;
            if (rrow >= M) continue;
            #pragma unroll
            for (int nt = 0; nt < 4; nt++) {
                int ccol = col0 + wn * 32 + nt * 8 + cl2;
                float v0 = acc[mt][nt][half * 2 + 0];
                float v1 = acc[mt][nt][half * 2 + 1];
                if (bias) { v0 += bias[ccol]; v1 += bias[ccol + 1]; }
                if (act == ACT_GELU) { v0 = gelu_tanh(v0); v1 = gelu_tanh(v1); }
                size_t off = (size_t)rrow * Nn + ccol;
                if (res) { v0 += res[off]; v1 += res[off + 1]; }
                C[off] = v0; C[off + 1] = v1;
            }
        }
    }
}

__global__ __launch_bounds__(256) void tgemm_kernel(
    const float* __restrict__ A, const float* __restrict__ W,
    const float* __restrict__ bias, const float* __restrict__ res,
    float* __restrict__ C, int M, int Nn, int K, int act)
{
    PlainA ld; ld.A = A; ld.K = K;
    tgemm_body(ld, W, bias, res, C, M, Nn, K, act, blockIdx.y * 128, blockIdx.x * 64);
}

__global__ __launch_bounds__(256) void qkv_tgemm_kernel(
    const float* __restrict__ h,
    const float* __restrict__ Wq, const float* __restrict__ Wk,
    const float* __restrict__ Wv,
    float* __restrict__ q, float* __restrict__ k, float* __restrict__ v)
{
    int bx = blockIdx.x;
    int sel = bx >> 3;
    const float* W; float* C;
    if (sel == 0)      { W = Wq; C = q; }
    else if (sel == 1) { W = Wk; C = k; }
    else               { W = Wv; C = v; }
    PlainA ld; ld.A = h; ld.K = DIMM;
    tgemm_body(ld, W, (const float*)0, (const float*)0, C, BN, DIMM, DIMM,
               ACT_NONE, blockIdx.y * 128, (bx & 7) * 64);
}

__global__ __launch_bounds__(256) void compress_tgemm_kernel(
    const float* __restrict__ kin, const float* __restrict__ vin,
    const float* __restrict__ kpe, const float* __restrict__ vpe,
    const float* __restrict__ Wkc, const float* __restrict__ Wvc,
    float* __restrict__ ck, float* __restrict__ cv)
{
    GatherA ld;
    const float* W; float* C;
    if (blockIdx.x == 0) { ld.kin = kin; ld.pe = kpe; W = Wkc; C = ck; }
    else                 { ld.kin = vin; ld.pe = vpe; W = Wvc; C = cv; }
    tgemm_body(ld, W, (const float*)0, (const float*)0, C, CM, 64, 1024,
               ACT_NONE, blockIdx.y * 128, 0);
}

// ---------------- patch embed + cls + pos ----------------
__global__ void patch_embed_kernel(const float* __restrict__ img,
                                   const float* __restrict__ pw,
                                   const float* __restrict__ pb,
                                   const float* __restrict__ pos,
                                   const float* __restrict__ cls,
                                   float* __restrict__ x) {
    int t = blockIdx.x % NTOK;
    int b = blockIdx.x / NTOK;
    for (int d = threadIdx.x; d < DIMM; d += blockDim.x) {
        float v;
        if (t == 0) {
            v = cls[d];
        } else {
            int p = t - 1;
            int ii = p / 24, jj = p % 24;
            v = pb[d];
            #pragma unroll
            for (int c = 0; c < 3; c++)
                v += img[((b * 3 + c) * 24 + ii) * 24 + jj] * pw[c * DIMM + d];
        }
        x[((size_t)(b * NTOK + t)) * DIMM + d] = v + pos[(size_t)t * DIMM + d];
    }
}

// ---------------- layernorm ----------------
__global__ __launch_bounds__(256) void ln_kernel(const float* __restrict__ in, long strideIn,
                          float* __restrict__ out,
                          const float* __restrict__ g, const float* __restrict__ bb) {
    __shared__ float sred[8];
    int r = blockIdx.x;
    const float* row = in + (size_t)r * strideIn;
    int t = threadIdx.x;
    float a0 = row[t], a1 = row[t + 256];
    float mean = blk_sum256(a0 + a1, sred) * (1.0f / 512.0f);
    float d0 = a0 - mean, d1 = a1 - mean;
    __syncthreads();
    float var = blk_sum256(d0 * d0 + d1 * d1, sred) * (1.0f / 512.0f);
    float inv = rsqrtf(var + 1e-5f);
    out[(size_t)r * DIMM + t]       = d0 * inv * g[t] + bb[t];
    out[(size_t)r * DIMM + t + 256] = d1 * inv * g[t + 256] + bb[t + 256];
}

// ---------------- fp32 SGEMM (gate + head path) ----------------
__global__ __launch_bounds__(256) void sgemm_kernel(
    const float* __restrict__ A, const float* __restrict__ W,
    const float* __restrict__ bias, const float* __restrict__ res,
    float* __restrict__ C, int M, int Nn, int K, int act)
{
    __shared__ __align__(16) float As[2][16][68];
    __shared__ __align__(16) float Bs[2][16][64];
    int tid = threadIdx.x;
    int tx = tid & 15, ty = tid >> 4;
    int row0 = blockIdx.y * 64, col0 = blockIdx.x * 64;

    int am  = tid >> 2;
    int akq = tid & 3;
    int arow = row0 + am;
    const float* Aptr = (arow < M) ? (A + (size_t)arow * K + akq * 4) : (const float*)0;
    int bkk = tid >> 4;
    int bnq = tid & 15;
    int bcol = col0 + bnq * 4;
    const float* Wptr = W + (size_t)bkk * Nn + bcol;
    bool bfull = (bcol + 3 < Nn);
    bool bany  = (bcol < Nn);

    float4 a4, b4;
    if (Aptr) a4 = *(const float4*)(Aptr);
    else      a4 = make_float4(0.f, 0.f, 0.f, 0.f);
    if (bfull) b4 = *(const float4*)(Wptr);
    else {
        b4 = make_float4(0.f, 0.f, 0.f, 0.f);
        if (bany) {
            b4.x = Wptr[0];
            if (bcol + 1 < Nn) b4.y = Wptr[1];
            if (bcol + 2 < Nn) b4.z = Wptr[2];
        }
    }
    As[0][akq * 4 + 0][am] = a4.x;
    As[0][akq * 4 + 1][am] = a4.y;
    As[0][akq * 4 + 2][am] = a4.z;
    As[0][akq * 4 + 3][am] = a4.w;
    *(float4*)&Bs[0][bkk][bnq * 4] = b4;
    __syncthreads();

    float acc[4][4];
    #pragma unroll
    for (int i = 0; i < 4; i++)
        #pragma unroll
        for (int j = 0; j < 4; j++) acc[i][j] = 0.f;

    int steps = K >> 4;
    for (int ks = 0; ks < steps; ks++) {
        int cur = ks & 1;
        bool hn = (ks + 1 < steps);
        if (hn) {
            int k0 = (ks + 1) * 16;
            if (Aptr) a4 = *(const float4*)(Aptr + k0);
            else      a4 = make_float4(0.f, 0.f, 0.f, 0.f);
            if (bfull) b4 = *(const float4*)(Wptr + (size_t)k0 * Nn);
            else {
                b4 = make_float4(0.f, 0.f, 0.f, 0.f);
                if (bany) {
                    const float* p = Wptr + (size_t)k0 * Nn;
                    b4.x = p[0];
                    if (bcol + 1 < Nn) b4.y = p[1];
                    if (bcol + 2 < Nn) b4.z = p[2];
                }
            }
        }
        #pragma unroll
        for (int kk = 0; kk < 16; kk++) {
            float4 av = *(const float4*)&As[cur][kk][ty * 4];
            float4 bv = *(const float4*)&Bs[cur][kk][tx * 4];
            acc[0][0] += av.x * bv.x; acc[0][1] += av.x * bv.y; acc[0][2] += av.x * bv.z; acc[0][3] += av.x * bv.w;
            acc[1][0] += av.y * bv.x; acc[1][1] += av.y * bv.y; acc[1][2] += av.y * bv.z; acc[1][3] += av.y * bv.w;
            acc[2][0] += av.z * bv.x; acc[2][1] += av.z * bv.y; acc[2][2] += av.z * bv.z; acc[2][3] += av.z * bv.w;
            acc[3][0] += av.w * bv.x; acc[3][1] += av.w * bv.y; acc[3][2] += av.w * bv.z; acc[3][3] += av.w * bv.w;
        }
        if (hn) {
            int nxt = cur ^ 1;
            As[nxt][akq * 4 + 0][am] = a4.x;
            As[nxt][akq * 4 + 1][am] = a4.y;
            As[nxt][akq * 4 + 2][am] = a4.z;
            As[nxt][akq * 4 + 3][am] = a4.w;
            *(float4*)&Bs[nxt][bkk][bnq * 4] = b4;
            __syncthreads();
        }
    }
    #pragma unroll
    for (int i = 0; i < 4; i++) {
        int r = row0 + ty * 4 + i;
        if (r >= M) continue;
        #pragma unroll
        for (int j = 0; j < 4; j++) {
            int c = col0 + tx * 4 + j;
            if (c >= Nn) continue;
            float v = acc[i][j];
            if (bias) v += bias[c];
            if (act == ACT_GELU) v = gelu_tanh(v);
            else if (act == ACT_SIG) v = 1.0f / (1.0f + expf(-v));
            if (res) v += res[(size_t)r * Nn + c];
            C[(size_t)r * Nn + c] = v;
        }
    }
}

// ---------------- compressed attention + top-k (8 queries/block) ----------------
__global__ __launch_bounds__(256) void cattn_kernel(
    const float* __restrict__ q, const float* __restrict__ ck,
    const float* __restrict__ cv, float* __restrict__ outc,
    int* __restrict__ selb)
{
    __shared__ float cbuf[NCC * 65];
    __shared__ float qs[QC * 64];
    __shared__ float sc[QC][NCC];
    int blk = blockIdx.x;
    int qb = blk % NQB, bh = blk / NQB;
    int h = bh % HH, b = bh / HH;
    int i0 = qb * QC;
    int tid = threadIdx.x;
    for (int idx = tid; idx < QC * 64; idx += 256) {
        int u = idx >> 6, d2 = idx & 63, i = i0 + u;
        qs[idx] = (i < NTOK) ? q[((size_t)(b * NTOK + i)) * DIMM + h * DHH + d2] : 0.f;
    }
    const float* ckb = ck + (size_t)bh * NCC * DHH;
    for (int idx = tid; idx < NCC * 64; idx += 256) {
        int j = idx >> 6, d2 = idx & 63;
        cbuf[j * 65 + d2] = ckb[idx];
    }
    __syncthreads();
    for (int p = tid; p < QC * NCC; p += 256) {
        int u = p / NCC, j = p % NCC;
        const float* cr = &cbuf[j * 65];
        const float* qr = &qs[u * 64];
        float a = 0.f;
        #pragma unroll
        for (int d2 = 0; d2 < 64; d2++) a += qr[d2] * cr[d2];
        sc[u][j] = a * 0.125f;
    }
    __syncthreads();
    int w = tid >> 5, ln = tid & 31;
    {
        float m = -1e30f;
        for (int j = ln; j < NCC; j += 32) m = fmaxf(m, sc[w][j]);
        #pragma unroll
        for (int o = 16; o; o >>= 1) m = fmaxf(m, __shfl_xor_sync(0xffffffffu, m, o));
        float s = 0.f;
        for (int j = ln; j < NCC; j += 32) { float e = expf(sc[w][j] - m); sc[w][j] = e; s += e; }
        #pragma unroll
        for (int o = 16; o; o >>= 1) s += __shfl_xor_sync(0xffffffffu, s, o);
        float inv = 1.f / s;
        for (int j = ln; j < NCC; j += 32) sc[w][j] *= inv;
    }
    __syncthreads();
    if (tid < QC) {
        int i = i0 + tid;
        if (i < NTOK) {
            float imp[NSB];
            #pragma unroll
            for (int t = 0; t < NSB; t++) imp[t] = 0.f;
            for (int j = 0; j < NCC; j++) {
                int c = (j + 2) >> 4; if (c > NSB - 1) c = NSB - 1;
                imp[c] += sc[tid][j];
            }
            size_t gi = (size_t)bh * NTOK + i;
            #pragma unroll
            for (int t = 0; t < KSEL; t++) {
                float best = -1e30f; int bi = 0;
                #pragma unroll
                for (int sbv = 0; sbv < NSB; sbv++)
                    if (imp[sbv] > best) { best = imp[sbv]; bi = sbv; }
                selb[gi * KSEL + t] = bi;
                imp[bi] = -2e30f;
            }
        }
    }
    __syncthreads();
    const float* cvb = cv + (size_t)bh * NCC * DHH;
    for (int idx = tid; idx < NCC * 64; idx += 256) {
        int j = idx >> 6, d2 = idx & 63;
        cbuf[j * 65 + d2] = cvb[idx];
    }
    __syncthreads();
    for (int p = tid; p < QC * 64; p += 256) {
        int u = p >> 6, d2 = p & 63;
        int i = i0 + u;
        if (i >= NTOK) continue;
        float a = 0.f;
        for (int j = 0; j < NCC; j++) a += sc[u][j] * cbuf[j * 65 + d2];
        outc[((size_t)(bh * NTOK + i)) * 64 + d2] = a;
    }
}

// ---------------- selected-block attention ----------------
__global__ __launch_bounds__(256) void sattn_kernel(
    const float* __restrict__ q, const float* __restrict__ k,
    const float* __restrict__ v, const int* __restrict__ selb,
    float* __restrict__ outs)
{
    __shared__ float qs[64];
    __shared__ float kv[64 * 65];
    __shared__ float ss[256];
    __shared__ float part[256];
    __shared__ float sred[8];
    __shared__ int sb[4];
    int gi = blockIdx.x;
    int i = gi % NTOK;
    int bh = gi / NTOK;
    int h = bh % HH, b = bh / HH;
    int tid = threadIdx.x;
    if (tid < 64) qs[tid] = q[((size_t)(b * NTOK + i)) * DIMM + h * DHH + tid];
    if (tid < 4) sb[tid] = selb[(size_t)gi * KSEL + tid];
    __syncthreads();
    const float* kbase = k + (size_t)b * NTOK * DIMM + h * DHH;
    int tt = tid & 63, ds = tid >> 6;
    for (int c = 0; c < 4; c++) {
        int blk = sb[c];
        for (int idx = tid; idx < 4096; idx += 256) {
            int t2 = idx >> 6, d2 = idx & 63;
            int tok = blk * 64 + t2; int tk = tok < NTOK ? tok : NTOK - 1;
            kv[t2 * 65 + d2] = kbase[(size_t)tk * DIMM + d2];
        }
        __syncthreads();
        float pp = 0.f;
        #pragma unroll
        for (int d = 0; d < 16; d++) pp += qs[ds * 16 + d] * kv[tt * 65 + ds * 16 + d];
        part[tid] = pp;
        __syncthreads();
        if (tid < 64) {
            float a = part[tid] + part[tid + 64] + part[tid + 128] + part[tid + 192];
            int tok = blk * 64 + tid;
            ss[c * 64 + tid] = (tok < NTOK) ? a * 0.125f : -1e30f;
        }
        __syncthreads();
    }
    float sv = ss[tid];
    float mx = blk_max256(sv, sred);
    float e = expf(sv - mx);
    __syncthreads();
    float tot = blk_sum256(e, sred);
    ss[tid] = e / tot;
    __syncthreads();
    const float* vbase = v + (size_t)b * NTOK * DIMM + h * DHH;
    int d = tid & 63; int ts = tid >> 6;
    float acc = 0.f;
    for (int c = 0; c < 4; c++) {
        int blk = sb[c];
        for (int idx = tid; idx < 4096; idx += 256) {
            int t2 = idx >> 6, d2 = idx & 63;
            int tok = blk * 64 + t2; int tk = tok < NTOK ? tok : NTOK - 1;
            kv[t2 * 65 + d2] = vbase[(size_t)tk * DIMM + d2];
        }
        __syncthreads();
        #pragma unroll
        for (int t = 0; t < 16; t++)
            acc += ss[c * 64 + ts * 16 + t] * kv[(ts * 16 + t) * 65 + d];
        __syncthreads();
    }
    part[tid] = acc;
    __syncthreads();
    if (tid < 64)
        outs[(size_t)gi * 64 + tid] =
            part[tid] + part[tid + 64] + part[tid + 128] + part[tid + 192];
}

// ---------------- sliding window attention + gate combine ----------------
__global__ __launch_bounds__(256) void wcomb_kernel(
    const float* __restrict__ q, const float* __restrict__ k,
    const float* __restrict__ v,
    const float* __restrict__ outc, const float* __restrict__ outs,
    const float* __restrict__ gate, float* __restrict__ attn)
{
    __shared__ float qs[64];
    __shared__ float sw[SWIN];
    __shared__ int   pcs[SWIN];
    __shared__ float part[256];
    int gi = blockIdx.x;
    int i = gi % NTOK;
    int bh = gi / NTOK;
    int h = bh % HH, b = bh / HH;
    int tid = threadIdx.x;
    if (tid < 64) qs[tid] = q[((size_t)(b * NTOK + i)) * DIMM + h * DHH + tid];
    __syncthreads();
    if (tid < SWIN) {
        int pos = i + tid - SWIN / 2;
        bool valid = (pos >= 0) && (pos < NTOK);
        int p = pos < 0 ? 0 : (pos > NTOK - 1 ? NTOK - 1 : pos);
        pcs[tid] = p;
        const float* kp = k + ((size_t)(b * NTOK + p)) * DIMM + h * DHH;
        float a = 0.f;
        #pragma unroll
        for (int d = 0; d < 64; d++) a += qs[d] * kp[d];
        float s = valid ? a * 0.125f : -1e30f;
        float mx = s;
        #pragma unroll
        for (int o = 16; o; o >>= 1) mx = fmaxf(mx, __shfl_xor_sync(0xffffffffu, mx, o));
        float e = expf(s - mx);
        float tot = e;
        #pragma unroll
        for (int o = 16; o; o >>= 1) tot += __shfl_xor_sync(0xffffffffu, tot, o);
        sw[tid] = e / tot;
    }
    __syncthreads();
    int ws = tid >> 6, d = tid & 63;
    const float* vbase = v + (size_t)b * NTOK * DIMM + h * DHH;
    float pp = 0.f;
    #pragma unroll
    for (int w2 = 0; w2 < 8; w2++) {
        int w = ws * 8 + w2;
        pp += sw[w] * vbase[(size_t)pcs[w] * DIMM + d];
    }
    part[tid] = pp;
    __syncthreads();
    if (tid < 64) {
        float ow = part[tid] + part[tid + 64] + part[tid + 128] + part[tid + 192];
        const float* gp = gate + ((size_t)(b * NTOK + i)) * 24 + h * 3;
        float oc = outc[(size_t)gi * 64 + tid];
        float os = outs[(size_t)gi * 64 + tid];
        attn[((size_t)(b * NTOK + i)) * DIMM + h * DHH + tid] =
            gp[0] * oc + gp[1] * os + gp[2] * ow;
    }
}

// ---------------- classifier head ----------------
__global__ void head_kernel(const float* __restrict__ hb, const float* __restrict__ W,
                            const float* __restrict__ bias, float* __restrict__ out)
{
    int o = blockIdx.y * 256 + threadIdx.x;
    int b = blockIdx.x;
    if (o >= NCLS) return;
    const float* hr = hb + b * DIMM;
    float acc = bias[o];
    for (int d = 0; d < DIMM; d++) acc += hr[d] * W[(size_t)d * NCLS + o];
    out[(size_t)b * NCLS + o] = acc;
}

// ---------------- launch ----------------
static inline void launch_tgemm(const float* A, const float* W, const float* bias,
                                const float* res, float* C, int M, int Nn, int K, int act) {
    dim3 grid(Nn / 64, (M + 127) / 128);
    tgemm_kernel<<<grid, 256>>>(A, W, bias, res, C, M, Nn, K, act);
}

extern "C" void kernel_launch(void* const* d_in, const int* in_sizes, int n_in,
                              void* d_out, int out_size) {
    const float* img     = (const float*)d_in[0];
    const float* patch_w = (const float*)d_in[1];
    const float* patch_b = (const float*)d_in[2];
    const float* pos_emb = (const float*)d_in[3];
    const float* cls_tok = (const float*)d_in[4];
    const float* ln1_g   = (const float*)d_in[5];
    const float* ln1_b   = (const float*)d_in[6];
    const float* Wq      = (const float*)d_in[7];
    const float* Wk      = (const float*)d_in[8];
    const float* Wv      = (const float*)d_in[9];
    const float* Wg      = (const float*)d_in[10];
    const float* Wo      = (const float*)d_in[11];
    const float* kpe     = (const float*)d_in[12];
    const float* vpe     = (const float*)d_in[13];
    const float* Wkc     = (const float*)d_in[14];
    const float* Wvc     = (const float*)d_in[15];
    const float* ln2_g   = (const float*)d_in[16];
    const float* ln2_b   = (const float*)d_in[17];
    const float* ff_w1   = (const float*)d_in[18];
    const float* ff_b1   = (const float*)d_in[19];
    const float* ff_w2   = (const float*)d_in[20];
    const float* ff_b2   = (const float*)d_in[21];
    const float* hln_g   = (const float*)d_in[22];
    const float* hln_b   = (const float*)d_in[23];
    const float* head_w  = (const float*)d_in[24];
    const float* head_b  = (const float*)d_in[25];

    float *x, *h, *q, *k, *v, *gate, *ck, *cv, *outc, *outs, *attn, *mlp, *hb;
    int* selb;
    cudaGetSymbolAddress((void**)&x, g_x);
    cudaGetSymbolAddress((void**)&h, g_h);
    cudaGetSymbolAddress((void**)&q, g_q);
    cudaGetSymbolAddress((void**)&k, g_k);
    cudaGetSymbolAddress((void**)&v, g_v);
    cudaGetSymbolAddress((void**)&gate, g_gate);
    cudaGetSymbolAddress((void**)&ck, g_ck);
    cudaGetSymbolAddress((void**)&cv, g_cv);
    cudaGetSymbolAddress((void**)&outc, g_outc);
    cudaGetSymbolAddress((void**)&outs, g_outs);
    cudaGetSymbolAddress((void**)&selb, g_selb);
    cudaGetSymbolAddress((void**)&attn, g_attn);
    cudaGetSymbolAddress((void**)&mlp, g_mlp);
    cudaGetSymbolAddress((void**)&hb, g_hb);

    patch_embed_kernel<<<BB * NTOK, 256>>>(img, patch_w, patch_b, pos_emb, cls_tok, x);

    for (int l = 0; l < 2; l++) {
        const float* Wql = Wq + (size_t)l * DIMM * DIMM;
        const float* Wkl = Wk + (size_t)l * DIMM * DIMM;
        const float* Wvl = Wv + (size_t)l * DIMM * DIMM;
        const float* Wgl = Wg + (size_t)l * DIMM * 24;
        const float* Wol = Wo + (size_t)l * DIMM * DIMM;
        const float* kpel = kpe + (size_t)l * 16 * DHH;
        const float* vpel = vpe + (size_t)l * 16 * DHH;
        const float* Wkcl = Wkc + (size_t)l * 1024 * DHH;
        const float* Wvcl = Wvc + (size_t)l * 1024 * DHH;

        ln_kernel<<<BN, 256>>>(x, DIMM, h, ln1_g + l * DIMM, ln1_b + l * DIMM);

        qkv_tgemm_kernel<<<dim3(24, 10), 256>>>(h, Wql, Wkl, Wvl, q, k, v);
        sgemm_kernel<<<dim3(1, 19), 256>>>(h, Wgl, (const float*)0, (const float*)0,
                                           gate, BN, 24, DIMM, ACT_SIG);

        compress_tgemm_kernel<<<dim3(2, (CM + 127) / 128), 256>>>(
            k, v, kpel, vpel, Wkcl, Wvcl, ck, cv);

        cattn_kernel<<<BB * HH * NQB, 256>>>(q, ck, cv, outc, selb);
        sattn_kernel<<<BB * HH * NTOK, 256>>>(q, k, v, selb, outs);
        wcomb_kernel<<<BB * HH * NTOK, 256>>>(q, k, v, outc, outs, gate, attn);

        launch_tgemm(attn, Wol, nullptr, x, x, BN, DIMM, DIMM, ACT_NONE);

        ln_kernel<<<BN, 256>>>(x, DIMM, h, ln2_g + l * DIMM, ln2_b + l * DIMM);
        launch_tgemm(h, ff_w1 + (size_t)l * DIMM * MLPD, ff_b1 + (size_t)l * MLPD,
                     nullptr, mlp, BN, MLPD, DIMM, ACT_GELU);
        launch_tgemm(mlp, ff_w2 + (size_t)l * MLPD * DIMM, ff_b2 + (size_t)l * DIMM,
                     x, x, BN, DIMM, MLPD, ACT_NONE);
    }

    ln_kernel<<<BB, 256>>>(x, (long)NTOK * DIMM, hb, hln_g, hln_b);
    head_kernel<<<dim3(BB, (NCLS + 255) / 256), 256>>>(hb, head_w, head_b, (float*)d_out);
}

// round 5
// speedup vs baseline: 1.5401x; 1.5401x over previous
#include <cuda_runtime.h>
#include <math.h>

// ---------------- problem constants ----------------
#define BB   2
#define NTOK 577
#define DIMM 512
#define HH   8
#define DHH  64
#define NCC  145
#define NSB  10
#define KSEL 4
#define SWIN 32
#define MLPD 2048
#define NCLS 1000
#define BN   (BB*NTOK)    // 1154
#define QC   8
#define NQB  73
#define NJC  37

#define ACT_NONE 0
#define ACT_GELU 1

// ---------------- device scratch ----------------
__device__ float g_x   [BN*DIMM];
__device__ float g_h   [BN*DIMM];
__device__ float g_q   [BN*DIMM];
__device__ float g_k   [BN*DIMM];
__device__ float g_v   [BN*DIMM];
__device__ float g_gate[BN*24];
__device__ float g_ck  [BB*HH*NCC*DHH];
__device__ float g_cv  [BB*HH*NCC*DHH];
__device__ float g_outc[BB*HH*NTOK*DHH];
__device__ float g_outs[BB*HH*NTOK*DHH];
__device__ int   g_selb[BB*HH*NTOK*KSEL];
__device__ float g_attn[BN*DIMM];
__device__ float g_mlp [BN*MLPD];
__device__ float g_part[4*BN*DIMM];   // split-K partials
__device__ float g_hb  [BB*DIMM];

// ---------------- helpers ----------------
__device__ __forceinline__ float gelu_tanh(float x) {
    float x3 = x * x * x;
    return 0.5f * x * (1.0f + tanhf(0.7978845608028654f * (x + 0.044715f * x3)));
}
__device__ __forceinline__ float blk_max256(float v, float* sred) {
    #pragma unroll
    for (int o = 16; o; o >>= 1) v = fmaxf(v, __shfl_xor_sync(0xffffffffu, v, o));
    __syncthreads();
    if ((threadIdx.x & 31) == 0) sred[threadIdx.x >> 5] = v;
    __syncthreads();
    float r = sred[0];
    #pragma unroll
    for (int w = 1; w < 8; w++) r = fmaxf(r, sred[w]);
    return r;
}
__device__ __forceinline__ float blk_sum256(float v, float* sred) {
    #pragma unroll
    for (int o = 16; o; o >>= 1) v += __shfl_xor_sync(0xffffffffu, v, o);
    __syncthreads();
    if ((threadIdx.x & 31) == 0) sred[threadIdx.x >> 5] = v;
    __syncthreads();
    float r = sred[0];
    #pragma unroll
    for (int w = 1; w < 8; w++) r += sred[w];
    return r;
}

// ================ 128x128 FFMA SGEMM, 8x8/thread, double-buffered ================
// Requires N % 128 == 0, kLen % 8 == 0. Row guards on M only.
__device__ __forceinline__ void gemm128_core(
    const float* __restrict__ A, const float* __restrict__ W,
    const float* __restrict__ bias, const float* __restrict__ res,
    float* __restrict__ C, float* __restrict__ part,
    int M, int N, int K, int act,
    int row0, int col0, int k0, int kLen)
{
    __shared__ __align__(16) float As[2][8][132];
    __shared__ __align__(16) float Bs[2][8][128];
    int tid = threadIdx.x;
    int tx = tid & 15, ty = tid >> 4;

    int aRow = tid >> 1;
    int aK = (tid & 1) * 4;
    int arow_g = row0 + aRow; if (arow_g >= M) arow_g = M - 1;
    const float* Ap = A + (size_t)arow_g * K + k0 + aK;

    int bK = tid >> 5;
    int bNq = (tid & 31) * 4;
    const float* Wp = W + (size_t)(k0 + bK) * N + col0 + bNq;

    float4 aReg = *(const float4*)Ap;
    float4 bReg = *(const float4*)Wp;

    float acc[2][2][4][4];
    #pragma unroll
    for (int p = 0; p < 2; p++)
        #pragma unroll
        for (int q = 0; q < 2; q++)
            #pragma unroll
            for (int i = 0; i < 4; i++)
                #pragma unroll
                for (int j = 0; j < 4; j++) acc[p][q][i][j] = 0.f;

    As[0][aK + 0][aRow] = aReg.x;
    As[0][aK + 1][aRow] = aReg.y;
    As[0][aK + 2][aRow] = aReg.z;
    As[0][aK + 3][aRow] = aReg.w;
    *(float4*)&Bs[0][bK][bNq] = bReg;
    __syncthreads();

    int steps = kLen >> 3;
    for (int s = 0; s < steps; s++) {
        int cur = s & 1;
        bool hn = (s + 1 < steps);
        if (hn) {
            aReg = *(const float4*)(Ap + (s + 1) * 8);
            bReg = *(const float4*)(Wp + (size_t)(s + 1) * 8 * N);
        }
        #pragma unroll
        for (int kk = 0; kk < 8; kk++) {
            float4 a0 = *(const float4*)&As[cur][kk][ty * 4];
            float4 a1 = *(const float4*)&As[cur][kk][64 + ty * 4];
            float4 b0 = *(const float4*)&Bs[cur][kk][tx * 4];
            float4 b1 = *(const float4*)&Bs[cur][kk][64 + tx * 4];
            float av0[4] = {a0.x, a0.y, a0.z, a0.w};
            float av1[4] = {a1.x, a1.y, a1.z, a1.w};
            float bv0[4] = {b0.x, b0.y, b0.z, b0.w};
            float bv1[4] = {b1.x, b1.y, b1.z, b1.w};
            #pragma unroll
            for (int i = 0; i < 4; i++)
                #pragma unroll
                for (int j = 0; j < 4; j++) {
                    acc[0][0][i][j] += av0[i] * bv0[j];
                    acc[0][1][i][j] += av0[i] * bv1[j];
                    acc[1][0][i][j] += av1[i] * bv0[j];
                    acc[1][1][i][j] += av1[i] * bv1[j];
                }
        }
        if (hn) {
            int nxt = cur ^ 1;
            As[nxt][aK + 0][aRow] = aReg.x;
            As[nxt][aK + 1][aRow] = aReg.y;
            As[nxt][aK + 2][aRow] = aReg.z;
            As[nxt][aK + 3][aRow] = aReg.w;
            *(float4*)&Bs[nxt][bK][bNq] = bReg;
            __syncthreads();
        }
    }

    #pragma unroll
    for (int qy = 0; qy < 2; qy++) {
        #pragma unroll
        for (int i = 0; i < 4; i++) {
            int r = row0 + qy * 64 + ty * 4 + i;
            if (r >= M) continue;
            #pragma unroll
            for (int qx = 0; qx < 2; qx++) {
                int c = col0 + qx * 64 + tx * 4;
                float4 v;
                v.x = acc[qy][qx][i][0]; v.y = acc[qy][qx][i][1];
                v.z = acc[qy][qx][i][2]; v.w = acc[qy][qx][i][3];
                size_t off = (size_t)r * N + c;
                if (part) {
                    *(float4*)(part + off) = v;
                } else {
                    if (bias) {
                        v.x += bias[c]; v.y += bias[c + 1];
                        v.z += bias[c + 2]; v.w += bias[c + 3];
                    }
                    if (act == ACT_GELU) {
                        v.x = gelu_tanh(v.x); v.y = gelu_tanh(v.y);
                        v.z = gelu_tanh(v.z); v.w = gelu_tanh(v.w);
                    }
                    if (res) {
                        float4 r4 = *(const float4*)(res + off);
                        v.x += r4.x; v.y += r4.y; v.z += r4.z; v.w += r4.w;
                    }
                    *(float4*)(C + off) = v;
                }
            }
        }
    }
}

__global__ __launch_bounds__(256) void gemm128_kernel(
    const float* __restrict__ A, const float* __restrict__ W,
    const float* __restrict__ bias, const float* __restrict__ res,
    float* __restrict__ C, int M, int N, int K, int act)
{
    gemm128_core(A, W, bias, res, C, (float*)0, M, N, K, act,
                 blockIdx.y * 128, blockIdx.x * 128, 0, K);
}

__global__ __launch_bounds__(256) void gemm128_split_kernel(
    const float* __restrict__ A, const float* __restrict__ W,
    float* __restrict__ part, int M, int N, int K)
{
    int S = gridDim.z;
    int chunk = K / S;
    float* p = part + (size_t)blockIdx.z * M * N;
    gemm128_core(A, W, (const float*)0, (const float*)0, (float*)0, p,
                 M, N, K, ACT_NONE,
                 blockIdx.y * 128, blockIdx.x * 128, blockIdx.z * chunk, chunk);
}

// reduce S split-K partial slices + bias + res -> C (float4 per thread)
__global__ __launch_bounds__(256) void reduce4_kernel(
    const float* __restrict__ part, const float* __restrict__ bias,
    const float* __restrict__ res, float* __restrict__ C,
    int N, int MN4, int S)
{
    int idx = blockIdx.x * 256 + threadIdx.x;
    if (idx >= MN4) return;
    size_t off = (size_t)idx * 4;
    size_t stride = (size_t)MN4 * 4;
    float4 s = *(const float4*)(part + off);
    for (int t = 1; t < S; t++) {
        float4 p = *(const float4*)(part + (size_t)t * stride + off);
        s.x += p.x; s.y += p.y; s.z += p.z; s.w += p.w;
    }
    if (bias) {
        int c = (int)(off % N);
        s.x += bias[c]; s.y += bias[c + 1]; s.z += bias[c + 2]; s.w += bias[c + 3];
    }
    if (res) {
        float4 r = *(const float4*)(res + off);
        s.x += r.x; s.y += r.y; s.z += r.z; s.w += r.w;
    }
    *(float4*)(C + off) = s;
}

// fused QKV (3x 1154x512x512), grid (12, 10)
__global__ __launch_bounds__(256) void qkv_gemm_kernel(
    const float* __restrict__ h,
    const float* __restrict__ Wq, const float* __restrict__ Wk,
    const float* __restrict__ Wv,
    float* __restrict__ q, float* __restrict__ k, float* __restrict__ v)
{
    int bx = blockIdx.x;
    int sel = bx >> 2;
    const float* W; float* C;
    if (sel == 0)      { W = Wq; C = q; }
    else if (sel == 1) { W = Wk; C = k; }
    else               { W = Wv; C = v; }
    gemm128_core(h, W, (const float*)0, (const float*)0, C, (float*)0,
                 BN, DIMM, DIMM, ACT_NONE, blockIdx.y * 128, (bx & 3) * 128, 0, DIMM);
}

// ---------------- gate projection (N=24): warp per row, Wg staged in smem ----------------
__global__ __launch_bounds__(256) void gate_kernel(
    const float* __restrict__ h, const float* __restrict__ Wg,
    float* __restrict__ gate)
{
    __shared__ float wgs[512 * 24];
    int tid = threadIdx.x;
    for (int i = tid; i < 512 * 24; i += 256) wgs[i] = Wg[i];
    __syncthreads();
    int warp = tid >> 5, lane = tid & 31;
    int row = blockIdx.x * 8 + warp;
    if (row >= BN) return;
    const float* hr = h + (size_t)row * 512;
    float acc[24];
    #pragma unroll
    for (int o = 0; o < 24; o++) acc[o] = 0.f;
    #pragma unroll
    for (int j = 0; j < 16; j++) {
        int k = j * 32 + lane;
        float hv = hr[k];
        const float* wr = &wgs[k * 24];
        #pragma unroll
        for (int o = 0; o < 24; o++) acc[o] += hv * wr[o];
    }
    #pragma unroll
    for (int o = 0; o < 24; o++) {
        #pragma unroll
        for (int off = 16; off; off >>= 1)
            acc[o] += __shfl_xor_sync(0xffffffffu, acc[o], off);
    }
    if (lane == 0) {
        float* gp = gate + (size_t)row * 24;
        #pragma unroll
        for (int o = 0; o < 24; o++) gp[o] = 1.f / (1.f + expf(-acc[o]));
    }
}

// ---------------- patch embed + cls + pos ----------------
__global__ void patch_embed_kernel(const float* __restrict__ img,
                                   const float* __restrict__ pw,
                                   const float* __restrict__ pb,
                                   const float* __restrict__ pos,
                                   const float* __restrict__ cls,
                                   float* __restrict__ x) {
    int t = blockIdx.x % NTOK;
    int b = blockIdx.x / NTOK;
    for (int d = threadIdx.x; d < DIMM; d += blockDim.x) {
        float v;
        if (t == 0) {
            v = cls[d];
        } else {
            int p = t - 1;
            int ii = p / 24, jj = p % 24;
            v = pb[d];
            #pragma unroll
            for (int c = 0; c < 3; c++)
                v += img[((b * 3 + c) * 24 + ii) * 24 + jj] * pw[c * DIMM + d];
        }
        x[((size_t)(b * NTOK + t)) * DIMM + d] = v + pos[(size_t)t * DIMM + d];
    }
}

// ---------------- layernorm ----------------
__global__ __launch_bounds__(256) void ln_kernel(const float* __restrict__ in, long strideIn,
                          float* __restrict__ out,
                          const float* __restrict__ g, const float* __restrict__ bb) {
    __shared__ float sred[8];
    int r = blockIdx.x;
    const float* row = in + (size_t)r * strideIn;
    int t = threadIdx.x;
    float a0 = row[t], a1 = row[t + 256];
    float mean = blk_sum256(a0 + a1, sred) * (1.0f / 512.0f);
    float d0 = a0 - mean, d1 = a1 - mean;
    __syncthreads();
    float var = blk_sum256(d0 * d0 + d1 * d1, sred) * (1.0f / 512.0f);
    float inv = rsqrtf(var + 1e-5f);
    out[(size_t)r * DIMM + t]       = d0 * inv * g[t] + bb[t];
    out[(size_t)r * DIMM + t + 256] = d1 * inv * g[t + 256] + bb[t + 256];
}

// ---------------- compress projection (k and v fused via blockIdx.y) ----------------
__global__ __launch_bounds__(256) void compress_kernel(
    const float* __restrict__ kin, const float* __restrict__ vin,
    const float* __restrict__ kpe, const float* __restrict__ vpe,
    const float* __restrict__ Wkc, const float* __restrict__ Wvc,
    float* __restrict__ cko, float* __restrict__ cvo)
{
    const float* in; const float* pe; const float* Wc; float* out;
    if (blockIdx.y == 0) { in = kin; pe = kpe; Wc = Wkc; out = cko; }
    else                 { in = vin; pe = vpe; Wc = Wvc; out = cvo; }
    __shared__ float kw[4][1024];
    __shared__ float part[4][4][64];
    int bx = blockIdx.x;
    int jc = bx % NJC, bh = bx / NJC;
    int h = bh % HH, b = bh / HH;
    int tid = threadIdx.x;
    for (int idx = tid; idx < 4096; idx += 256) {
        int jl = idx >> 10, e = idx & 1023;
        int jj = e >> 6, d = e & 63;
        int j = jc * 4 + jl;
        int tok = j * 4 + jj;
        float val = (j < NCC && tok < NTOK)
            ? in[((size_t)(b * NTOK + tok)) * DIMM + h * DHH + d] : 0.f;
        kw[jl][e] = val + pe[e];
    }
    __syncthreads();
    int es = tid >> 6, d = tid & 63;
    float a0 = 0.f, a1 = 0.f, a2 = 0.f, a3 = 0.f;
    int e0 = es * 256;
    for (int e = e0; e < e0 + 256; e++) {
        float wv = Wc[(size_t)e * 64 + d];
        a0 += kw[0][e] * wv; a1 += kw[1][e] * wv;
        a2 += kw[2][e] * wv; a3 += kw[3][e] * wv;
    }
    part[0][es][d] = a0; part[1][es][d] = a1;
    part[2][es][d] = a2; part[3][es][d] = a3;
    __syncthreads();
    int jl = tid >> 6;
    int j = jc * 4 + jl;
    if (j < NCC) {
        out[((size_t)(bh * NCC + j)) * 64 + d] =
            part[jl][0][d] + part[jl][1][d] + part[jl][2][d] + part[jl][3][d];
    }
}

// ---------------- compressed attention + top-k (8 queries/block) ----------------
__global__ __launch_bounds__(256) void cattn_kernel(
    const float* __restrict__ q, const float* __restrict__ ck,
    const float* __restrict__ cv, float* __restrict__ outc,
    int* __restrict__ selb)
{
    __shared__ float cbuf[NCC * 65];
    __shared__ float qs[QC * 64];
    __shared__ float sc[QC][NCC];
    int blk = blockIdx.x;
    int qb = blk % NQB, bh = blk / NQB;
    int h = bh % HH, b = bh / HH;
    int i0 = qb * QC;
    int tid = threadIdx.x;
    for (int idx = tid; idx < QC * 64; idx += 256) {
        int u = idx >> 6, d2 = idx & 63, i = i0 + u;
        qs[idx] = (i < NTOK) ? q[((size_t)(b * NTOK + i)) * DIMM + h * DHH + d2] : 0.f;
    }
    const float* ckb = ck + (size_t)bh * NCC * DHH;
    for (int idx = tid; idx < NCC * 64; idx += 256) {
        int j = idx >> 6, d2 = idx & 63;
        cbuf[j * 65 + d2] = ckb[idx];
    }
    __syncthreads();
    for (int p = tid; p < QC * NCC; p += 256) {
        int u = p / NCC, j = p % NCC;
        const float* cr = &cbuf[j * 65];
        const float* qr = &qs[u * 64];
        float a = 0.f;
        #pragma unroll
        for (int d2 = 0; d2 < 64; d2++) a += qr[d2] * cr[d2];
        sc[u][j] = a * 0.125f;
    }
    __syncthreads();
    int w = tid >> 5, ln = tid & 31;
    {
        float m = -1e30f;
        for (int j = ln; j < NCC; j += 32) m = fmaxf(m, sc[w][j]);
        #pragma unroll
        for (int o = 16; o; o >>= 1) m = fmaxf(m, __shfl_xor_sync(0xffffffffu, m, o));
        float s = 0.f;
        for (int j = ln; j < NCC; j += 32) { float e = expf(sc[w][j] - m); sc[w][j] = e; s += e; }
        #pragma unroll
        for (int o = 16; o; o >>= 1) s += __shfl_xor_sync(0xffffffffu, s, o);
        float inv = 1.f / s;
        for (int j = ln; j < NCC; j += 32) sc[w][j] *= inv;
    }
    __syncthreads();
    if (tid < QC) {
        int i = i0 + tid;
        if (i < NTOK) {
            float imp[NSB];
            #pragma unroll
            for (int t = 0; t < NSB; t++) imp[t] = 0.f;
            for (int j = 0; j < NCC; j++) {
                int c = (j + 2) >> 4; if (c > NSB - 1) c = NSB - 1;
                imp[c] += sc[tid][j];
            }
            size_t gi = (size_t)bh * NTOK + i;
            #pragma unroll
            for (int t = 0; t < KSEL; t++) {
                float best = -1e30f; int bi = 0;
                #pragma unroll
                for (int sbv = 0; sbv < NSB; sbv++)
                    if (imp[sbv] > best) { best = imp[sbv]; bi = sbv; }
                selb[gi * KSEL + t] = bi;
                imp[bi] = -2e30f;
            }
        }
    }
    __syncthreads();
    const float* cvb = cv + (size_t)bh * NCC * DHH;
    for (int idx = tid; idx < NCC * 64; idx += 256) {
        int j = idx >> 6, d2 = idx & 63;
        cbuf[j * 65 + d2] = cvb[idx];
    }
    __syncthreads();
    for (int p = tid; p < QC * 64; p += 256) {
        int u = p >> 6, d2 = p & 63;
        int i = i0 + u;
        if (i >= NTOK) continue;
        float a = 0.f;
        for (int j = 0; j < NCC; j++) a += sc[u][j] * cbuf[j * 65 + d2];
        outc[((size_t)(bh * NTOK + i)) * 64 + d2] = a;
    }
}

// ---------------- selected-block attention ----------------
__global__ __launch_bounds__(256) void sattn_kernel(
    const float* __restrict__ q, const float* __restrict__ k,
    const float* __restrict__ v, const int* __restrict__ selb,
    float* __restrict__ outs)
{
    __shared__ float qs[64];
    __shared__ float kv[64 * 65];
    __shared__ float ss[256];
    __shared__ float part[256];
    __shared__ float sred[8];
    __shared__ int sb[4];
    int gi = blockIdx.x;
    int i = gi % NTOK;
    int bh = gi / NTOK;
    int h = bh % HH, b = bh / HH;
    int tid = threadIdx.x;
    if (tid < 64) qs[tid] = q[((size_t)(b * NTOK + i)) * DIMM + h * DHH + tid];
    if (tid < 4) sb[tid] = selb[(size_t)gi * KSEL + tid];
    __syncthreads();
    const float* kbase = k + (size_t)b * NTOK * DIMM + h * DHH;
    int tt = tid & 63, ds = tid >> 6;
    for (int c = 0; c < 4; c++) {
        int blk = sb[c];
        for (int idx = tid; idx < 4096; idx += 256) {
            int t2 = idx >> 6, d2 = idx & 63;
            int tok = blk * 64 + t2; int tk = tok < NTOK ? tok : NTOK - 1;
            kv[t2 * 65 + d2] = kbase[(size_t)tk * DIMM + d2];
        }
        __syncthreads();
        float pp = 0.f;
        #pragma unroll
        for (int d = 0; d < 16; d++) pp += qs[ds * 16 + d] * kv[tt * 65 + ds * 16 + d];
        part[tid] = pp;
        __syncthreads();
        if (tid < 64) {
            float a = part[tid] + part[tid + 64] + part[tid + 128] + part[tid + 192];
            int tok = blk * 64 + tid;
            ss[c * 64 + tid] = (tok < NTOK) ? a * 0.125f : -1e30f;
        }
        __syncthreads();
    }
    float sv = ss[tid];
    float mx = blk_max256(sv, sred);
    float e = expf(sv - mx);
    __syncthreads();
    float tot = blk_sum256(e, sred);
    ss[tid] = e / tot;
    __syncthreads();
    const float* vbase = v + (size_t)b * NTOK * DIMM + h * DHH;
    int d = tid & 63; int ts = tid >> 6;
    float acc = 0.f;
    for (int c = 0; c < 4; c++) {
        int blk = sb[c];
        for (int idx = tid; idx < 4096; idx += 256) {
            int t2 = idx >> 6, d2 = idx & 63;
            int tok = blk * 64 + t2; int tk = tok < NTOK ? tok : NTOK - 1;
            kv[t2 * 65 + d2] = vbase[(size_t)tk * DIMM + d2];
        }
        __syncthreads();
        #pragma unroll
        for (int t = 0; t < 16; t++)
            acc += ss[c * 64 + ts * 16 + t] * kv[(ts * 16 + t) * 65 + d];
        __syncthreads();
    }
    part[tid] = acc;
    __syncthreads();
    if (tid < 64)
        outs[(size_t)gi * 64 + tid] =
            part[tid] + part[tid + 64] + part[tid + 128] + part[tid + 192];
}

// ---------------- sliding window attention + gate combine ----------------
__global__ __launch_bounds__(256) void wcomb_kernel(
    const float* __restrict__ q, const float* __restrict__ k,
    const float* __restrict__ v,
    const float* __restrict__ outc, const float* __restrict__ outs,
    const float* __restrict__ gate, float* __restrict__ attn)
{
    __shared__ float qs[64];
    __shared__ float sw[SWIN];
    __shared__ int   pcs[SWIN];
    __shared__ float part[256];
    int gi = blockIdx.x;
    int i = gi % NTOK;
    int bh = gi / NTOK;
    int h = bh % HH, b = bh / HH;
    int tid = threadIdx.x;
    if (tid < 64) qs[tid] = q[((size_t)(b * NTOK + i)) * DIMM + h * DHH + tid];
    __syncthreads();
    if (tid < SWIN) {
        int pos = i + tid - SWIN / 2;
        bool valid = (pos >= 0) && (pos < NTOK);
        int p = pos < 0 ? 0 : (pos > NTOK - 1 ? NTOK - 1 : pos);
        pcs[tid] = p;
        const float* kp = k + ((size_t)(b * NTOK + p)) * DIMM + h * DHH;
        float a = 0.f;
        #pragma unroll
        for (int d = 0; d < 64; d++) a += qs[d] * kp[d];
        float s = valid ? a * 0.125f : -1e30f;
        float mx = s;
        #pragma unroll
        for (int o = 16; o; o >>= 1) mx = fmaxf(mx, __shfl_xor_sync(0xffffffffu, mx, o));
        float e = expf(s - mx);
        float tot = e;
        #pragma unroll
        for (int o = 16; o; o >>= 1) tot += __shfl_xor_sync(0xffffffffu, tot, o);
        sw[tid] = e / tot;
    }
    __syncthreads();
    int ws = tid >> 6, d = tid & 63;
    const float* vbase = v + (size_t)b * NTOK * DIMM + h * DHH;
    float pp = 0.f;
    #pragma unroll
    for (int w2 = 0; w2 < 8; w2++) {
        int w = ws * 8 + w2;
        pp += sw[w] * vbase[(size_t)pcs[w] * DIMM + d];
    }
    part[tid] = pp;
    __syncthreads();
    if (tid < 64) {
        float ow = part[tid] + part[tid + 64] + part[tid + 128] + part[tid + 192];
        const float* gp = gate + ((size_t)(b * NTOK + i)) * 24 + h * 3;
        float oc = outc[(size_t)gi * 64 + tid];
        float os = outs[(size_t)gi * 64 + tid];
        attn[((size_t)(b * NTOK + i)) * DIMM + h * DHH + tid] =
            gp[0] * oc + gp[1] * os + gp[2] * ow;
    }
}

// ---------------- classifier head ----------------
__global__ void head_kernel(const float* __restrict__ hb, const float* __restrict__ W,
                            const float* __restrict__ bias, float* __restrict__ out)
{
    int o = blockIdx.y * 256 + threadIdx.x;
    int b = blockIdx.x;
    if (o >= NCLS) return;
    const float* hr = hb + b * DIMM;
    float acc = bias[o];
    #pragma unroll 8
    for (int d = 0; d < DIMM; d++) acc += hr[d] * W[(size_t)d * NCLS + o];
    out[(size_t)b * NCLS + o] = acc;
}

// ---------------- launch ----------------
extern "C" void kernel_launch(void* const* d_in, const int* in_sizes, int n_in,
                              void* d_out, int out_size) {
    const float* img     = (const float*)d_in[0];
    const float* patch_w = (const float*)d_in[1];
    const float* patch_b = (const float*)d_in[2];
    const float* pos_emb = (const float*)d_in[3];
    const float* cls_tok = (const float*)d_in[4];
    const float* ln1_g   = (const float*)d_in[5];
    const float* ln1_b   = (const float*)d_in[6];
    const float* Wq      = (const float*)d_in[7];
    const float* Wk      = (const float*)d_in[8];
    const float* Wv      = (const float*)d_in[9];
    const float* Wg      = (const float*)d_in[10];
    const float* Wo      = (const float*)d_in[11];
    const float* kpe     = (const float*)d_in[12];
    const float* vpe     = (const float*)d_in[13];
    const float* Wkc     = (const float*)d_in[14];
    const float* Wvc     = (const float*)d_in[15];
    const float* ln2_g   = (const float*)d_in[16];
    const float* ln2_b   = (const float*)d_in[17];
    const float* ff_w1   = (const float*)d_in[18];
    const float* ff_b1   = (const float*)d_in[19];
    const float* ff_w2   = (const float*)d_in[20];
    const float* ff_b2   = (const float*)d_in[21];
    const float* hln_g   = (const float*)d_in[22];
    const float* hln_b   = (const float*)d_in[23];
    const float* head_w  = (const float*)d_in[24];
    const float* head_b  = (const float*)d_in[25];

    float *x, *h, *q, *k, *v, *gate, *ck, *cv, *outc, *outs, *attn, *mlp, *hb, *prt;
    int* selb;
    cudaGetSymbolAddress((void**)&x, g_x);
    cudaGetSymbolAddress((void**)&h, g_h);
    cudaGetSymbolAddress((void**)&q, g_q);
    cudaGetSymbolAddress((void**)&k, g_k);
    cudaGetSymbolAddress((void**)&v, g_v);
    cudaGetSymbolAddress((void**)&gate, g_gate);
    cudaGetSymbolAddress((void**)&ck, g_ck);
    cudaGetSymbolAddress((void**)&cv, g_cv);
    cudaGetSymbolAddress((void**)&outc, g_outc);
    cudaGetSymbolAddress((void**)&outs, g_outs);
    cudaGetSymbolAddress((void**)&selb, g_selb);
    cudaGetSymbolAddress((void**)&attn, g_attn);
    cudaGetSymbolAddress((void**)&mlp, g_mlp);
    cudaGetSymbolAddress((void**)&prt, g_part);
    cudaGetSymbolAddress((void**)&hb, g_hb);

    const int MN4 = (BN * DIMM) / 4;       // 147712
    const int RG  = (MN4 + 255) / 256;     // 577

    patch_embed_kernel<<<BB * NTOK, 256>>>(img, patch_w, patch_b, pos_emb, cls_tok, x);

    for (int l = 0; l < 2; l++) {
        const float* Wql = Wq + (size_t)l * DIMM * DIMM;
        const float* Wkl = Wk + (size_t)l * DIMM * DIMM;
        const float* Wvl = Wv + (size_t)l * DIMM * DIMM;
        const float* Wgl = Wg + (size_t)l * DIMM * 24;
        const float* Wol = Wo + (size_t)l * DIMM * DIMM;
        const float* kpel = kpe + (size_t)l * 16 * DHH;
        const float* vpel = vpe + (size_t)l * 16 * DHH;
        const float* Wkcl = Wkc + (size_t)l * 1024 * DHH;
        const float* Wvcl = Wvc + (size_t)l * 1024 * DHH;

        ln_kernel<<<BN, 256>>>(x, DIMM, h, ln1_g + l * DIMM, ln1_b + l * DIMM);

        qkv_gemm_kernel<<<dim3(12, 10), 256>>>(h, Wql, Wkl, Wvl, q, k, v);
        gate_kernel<<<145, 256>>>(h, Wgl, gate);

        compress_kernel<<<dim3(BB * HH * NJC, 2), 256>>>(k, v, kpel, vpel, Wkcl, Wvcl, ck, cv);

        cattn_kernel<<<BB * HH * NQB, 256>>>(q, ck, cv, outc, selb);
        sattn_kernel<<<BB * HH * NTOK, 256>>>(q, k, v, selb, outs);
        wcomb_kernel<<<BB * HH * NTOK, 256>>>(q, k, v, outc, outs, gate, attn);

        // Wo: split-K x4 + reduce (res = x, in-place)
        gemm128_split_kernel<<<dim3(4, 10, 4), 256>>>(attn, Wol, prt, BN, DIMM, DIMM);
        reduce4_kernel<<<RG, 256>>>(prt, (const float*)0, x, x, DIMM, MN4, 4);

        ln_kernel<<<BN, 256>>>(x, DIMM, h, ln2_g + l * DIMM, ln2_b + l * DIMM);

        // ff1: direct, GELU + bias
        gemm128_kernel<<<dim3(16, 10), 256>>>(h, ff_w1 + (size_t)l * DIMM * MLPD,
                                              ff_b1 + (size_t)l * MLPD, (const float*)0,
                                              mlp, BN, MLPD, DIMM, ACT_GELU);
        // ff2: split-K x4 + reduce (bias + res)
        gemm128_split_kernel<<<dim3(4, 10, 4), 256>>>(mlp, ff_w2 + (size_t)l * MLPD * DIMM,
                                                      prt, BN, DIMM, MLPD);
        reduce4_kernel<<<RG, 256>>>(prt, ff_b2 + (size_t)l * DIMM, x, x, DIMM, MN4, 4);
    }

    ln_kernel<<<BB, 256>>>(x, (long)NTOK * DIMM, hb, hln_g, hln_b);
    head_kernel<<<dim3(BB, (NCLS + 255) / 256), 256>>>(hb, head_w, head_b, (float*)d_out);
}